// round 3
// baseline (speedup 1.0000x reference)
#include <cuda_runtime.h>
#include <math.h>

#define DIM 1024
#define WARPS_PER_BLOCK 8
#define ROWS_PER_WARP 2
#define ROWS_PER_BLOCK (WARPS_PER_BLOCK * ROWS_PER_WARP)
#define NTHREADS (WARPS_PER_BLOCK * 32)

// Convert a loaded row (8 x float4) to packed int16x2 + partial sums.
__device__ __forceinline__ void convert_row(const float4* v, int* pk, int& sum, int& sumsq)
{
    #pragma unroll
    for (int j = 0; j < 8; j++) {
        const int a = __float2int_rn(v[j].x);
        const int b = __float2int_rn(v[j].y);
        const int c = __float2int_rn(v[j].z);
        const int d = __float2int_rn(v[j].w);
        pk[j * 2 + 0] = (a & 0xffff) | (b << 16);
        pk[j * 2 + 1] = (c & 0xffff) | (d << 16);
        sum   += a + b + c + d;
        sumsq += a * a + b * b + c * c + d * d;
    }
}

// Row statistics -> (mean, inv, ts). All-lane REDUX reductions.
__device__ __forceinline__ void row_stats(int sum, int sumsq, const int* s_lut,
                                          int& mean, int& inv, int& ts)
{
    sum   = __reduce_add_sync(0xffffffffu, sum);
    sumsq = __reduce_add_sync(0xffffffffu, sumsq);
    mean = (sum * 64) >> 16;                      // fixed-point mean, arithmetic shift
    const long long ssy = (long long)sumsq
                        - 2LL * (long long)mean * (long long)sum
                        + (long long)DIM * (long long)mean * (long long)mean;
    long long var = (ssy * 64) >> 16;
    if (var < 1) var = 1;
    const int k = 63 - __clzll((unsigned long long)var);  // floor(log2(var)), exact
    const int sa = k - 4;
    const int mant = (sa >= 0) ? (int)((var >> sa) & 15)
                               : (int)((var << (-sa)) & 15);
    inv = s_lut[((k & 1) << 4) | mant];
    ts = (k >> 1) + 15;                           // p + SHIFT(0) + Q_LUT(15)
}

__device__ __forceinline__ void epilogue(const int* pk, int mean, int inv, int ts,
                                         const int* s_w, const int* s_b,
                                         float4* orow, int lane)
{
    #pragma unroll
    for (int j = 0; j < 8; j++) {
        const int c4 = j * 32 + lane;             // int4 index; col = c4*4
        const int4 w4 = ((const int4*)s_w)[c4];
        const int4 b4 = ((const int4*)s_b)[c4];
        const int p0 = pk[j * 2 + 0];
        const int p1 = pk[j * 2 + 1];
        const int a = (p0 << 16) >> 16;           // arithmetic unpack (exact)
        const int b = p0 >> 16;
        const int c = (p1 << 16) >> 16;
        const int d = p1 >> 16;
        float4 o;
        long long t;
        t = (((long long)((a - mean) * inv) * (long long)w4.x) >> ts) + b4.x;
        o.x = (float)t * 0.00390625f;
        t = (((long long)((b - mean) * inv) * (long long)w4.y) >> ts) + b4.y;
        o.y = (float)t * 0.00390625f;
        t = (((long long)((c - mean) * inv) * (long long)w4.z) >> ts) + b4.z;
        o.z = (float)t * 0.00390625f;
        t = (((long long)((d - mean) * inv) * (long long)w4.w) >> ts) + b4.w;
        o.w = (float)t * 0.00390625f;
        orow[j * 32 + lane] = o;
    }
}

__global__ __launch_bounds__(NTHREADS, 4)
void iln_kernel(const float* __restrict__ x,
                const float* __restrict__ weight,
                const float* __restrict__ bias,
                float* __restrict__ out,
                int n_rows)
{
    __shared__ int s_w[DIM];
    __shared__ int s_b[DIM];
    __shared__ int s_lut[32];

    const int tid = threadIdx.x;

    // 32-entry isqrt LUT, exact: round((1<<15)/sqrt(2^parity*(1+m/16)))
    if (tid < 32) {
        const int parity = tid >> 4;
        const int mant = tid & 15;
        const double val = (double)(1 << parity) * (1.0 + (double)mant * 0.0625);
        s_lut[tid] = (int)llrint(32768.0 / sqrt(val));
    }
    // Quantize weight/bias (round-half-even matches jnp.round)
    for (int i = tid; i < DIM; i += NTHREADS) {
        s_w[i] = __float2int_rn(weight[i] * 256.0f);
        s_b[i] = __float2int_rn(bias[i] * 256.0f);
    }
    __syncthreads();

    const int warp = tid >> 5;
    const int lane = tid & 31;
    const int rowA = blockIdx.x * ROWS_PER_BLOCK + warp * ROWS_PER_WARP;
    const int rowB = rowA + 1;
    if (rowA >= n_rows) return;

    const float4* __restrict__ xA = (const float4*)(x + (size_t)rowA * DIM);
    float4* __restrict__ oA = (float4*)(out + (size_t)rowA * DIM);

    // ---- Row A loads ----
    float4 va[8];
    #pragma unroll
    for (int j = 0; j < 8; j++) va[j] = xA[j * 32 + lane];

    int pkA[16];
    int sumA = 0, sqA = 0;
    convert_row(va, pkA, sumA, sqA);

    // ---- Issue Row B loads BEFORE row A's reduce/epilogue (latency overlap) ----
    const bool hasB = (rowB < n_rows);
    const float4* __restrict__ xB = (const float4*)(x + (size_t)rowB * DIM);
    float4 vb[8];
    if (hasB) {
        #pragma unroll
        for (int j = 0; j < 8; j++) vb[j] = xB[j * 32 + lane];
    }

    // ---- Row A stats + epilogue (hides B's DRAM latency) ----
    int meanA, invA, tsA;
    row_stats(sumA, sqA, s_lut, meanA, invA, tsA);
    epilogue(pkA, meanA, invA, tsA, s_w, s_b, oA, lane);

    // ---- Row B ----
    if (hasB) {
        int pkB[16];
        int sumB = 0, sqB = 0;
        convert_row(vb, pkB, sumB, sqB);
        int meanB, invB, tsB;
        row_stats(sumB, sqB, s_lut, meanB, invB, tsB);
        float4* __restrict__ oB = (float4*)(out + (size_t)rowB * DIM);
        epilogue(pkB, meanB, invB, tsB, s_w, s_b, oB, lane);
    }
}

extern "C" void kernel_launch(void* const* d_in, const int* in_sizes, int n_in,
                              void* d_out, int out_size) {
    const float* x      = (const float*)d_in[0];
    const float* weight = (const float*)d_in[1];
    const float* bias   = (const float*)d_in[2];
    // d_in[3] (isqrt_lut) intentionally unused: LUT recomputed exactly in-kernel.
    float* out = (float*)d_out;

    const int n_rows = in_sizes[0] / DIM;
    const int blocks = (n_rows + ROWS_PER_BLOCK - 1) / ROWS_PER_BLOCK;
    iln_kernel<<<blocks, NTHREADS>>>(x, weight, bias, out, n_rows);
}

// round 4
// speedup vs baseline: 1.5090x; 1.5090x over previous
#include <cuda_runtime.h>
#include <math.h>

#define DIM 1024
#define WARPS_PER_BLOCK 4
#define NTHREADS 128
#define GRID_BLOCKS 760          // ~5 blocks * 152 SMs
#define F4_PER_ROW 256           // 1024 floats = 256 float4
#define NSTAGE 2

__device__ __forceinline__ void cp_async16(void* smem_dst, const void* gsrc) {
    unsigned saddr = (unsigned)__cvta_generic_to_shared(smem_dst);
    asm volatile("cp.async.cg.shared.global [%0], [%1], 16;\n" :: "r"(saddr), "l"(gsrc));
}
__device__ __forceinline__ void cp_commit() { asm volatile("cp.async.commit_group;\n"); }
template<int N> __device__ __forceinline__ void cp_wait() {
    asm volatile("cp.async.wait_group %0;\n" :: "n"(N));
}

__global__ __launch_bounds__(NTHREADS)
void iln_kernel(const float* __restrict__ x,
                const float* __restrict__ weight,
                const float* __restrict__ bias,
                float* __restrict__ out,
                int n_rows)
{
    __shared__ int s_w[DIM];
    __shared__ int s_b[DIM];
    __shared__ int s_lut[32];
    __shared__ float4 s_x[WARPS_PER_BLOCK][NSTAGE][F4_PER_ROW];

    const int tid = threadIdx.x;

    // 32-entry isqrt LUT, exact: round((1<<15)/sqrt(2^parity*(1+m/16)))
    if (tid < 32) {
        const int parity = tid >> 4;
        const int mant = tid & 15;
        const double val = (double)(1 << parity) * (1.0 + (double)mant * 0.0625);
        s_lut[tid] = (int)llrint(32768.0 / sqrt(val));
    }
    // Quantize weight/bias (round-half-even matches jnp.round)
    for (int i = tid; i < DIM; i += NTHREADS) {
        s_w[i] = __float2int_rn(weight[i] * 256.0f);
        s_b[i] = __float2int_rn(bias[i] * 256.0f);
    }
    __syncthreads();

    const int warp = tid >> 5;
    const int lane = tid & 31;
    const int stride = GRID_BLOCKS * WARPS_PER_BLOCK;
    int row = blockIdx.x * WARPS_PER_BLOCK + warp;

    // Prologue prefetch
    if (row < n_rows) {
        const float4* __restrict__ xr = (const float4*)(x + (size_t)row * DIM);
        #pragma unroll
        for (int j = 0; j < 8; j++)
            cp_async16(&s_x[warp][0][j * 32 + lane], &xr[j * 32 + lane]);
        cp_commit();
    }

    int cur = 0;
    for (; row < n_rows; row += stride) {
        const int nxt = row + stride;
        if (nxt < n_rows) {
            const float4* __restrict__ xn = (const float4*)(x + (size_t)nxt * DIM);
            #pragma unroll
            for (int j = 0; j < 8; j++)
                cp_async16(&s_x[warp][cur ^ 1][j * 32 + lane], &xn[j * 32 + lane]);
            cp_commit();
            cp_wait<1>();        // wait only for the *current* row's group
        } else {
            cp_wait<0>();
        }

        // ---- process row from smem (thread reads exactly what it wrote) ----
        int pk[16];
        int sum = 0, sumsq = 0;  // sumsq max ~1e8 << 2^31, exact
        #pragma unroll
        for (int j = 0; j < 8; j++) {
            const float4 v = s_x[warp][cur][j * 32 + lane];
            const int a = __float2int_rn(v.x);
            const int b = __float2int_rn(v.y);
            const int c = __float2int_rn(v.z);
            const int d = __float2int_rn(v.w);
            pk[j * 2 + 0] = (a & 0xffff) | (b << 16);
            pk[j * 2 + 1] = (c & 0xffff) | (d << 16);
            sum   += a + b + c + d;
            sumsq += a * a + b * b + c * c + d * d;
        }

        sum   = __reduce_add_sync(0xffffffffu, sum);
        sumsq = __reduce_add_sync(0xffffffffu, sumsq);

        const int mean = (sum * 64) >> 16;                 // fixed-point mean
        const long long ssy = (long long)sumsq
                            - 2LL * (long long)mean * (long long)sum
                            + (long long)DIM * (long long)mean * (long long)mean;
        long long var = (ssy * 64) >> 16;
        if (var < 1) var = 1;

        const int k = 63 - __clzll((unsigned long long)var);   // floor(log2), exact
        const int sa = k - 4;
        const int mant = (sa >= 0) ? (int)((var >> sa) & 15)
                                   : (int)((var << (-sa)) & 15);
        const int inv = s_lut[((k & 1) << 4) | mant];
        const int ts = (k >> 1) + 15;                      // p + SHIFT(0) + Q_LUT(15)

        float4* __restrict__ orow = (float4*)(out + (size_t)row * DIM);
        #pragma unroll
        for (int j = 0; j < 8; j++) {
            const int c4 = j * 32 + lane;
            const int4 w4 = ((const int4*)s_w)[c4];
            const int4 b4 = ((const int4*)s_b)[c4];
            const int p0 = pk[j * 2 + 0];
            const int p1 = pk[j * 2 + 1];
            const int a = (p0 << 16) >> 16;                // arithmetic unpack
            const int b = p0 >> 16;
            const int c = (p1 << 16) >> 16;
            const int d = p1 >> 16;
            float4 o;
            long long t;
            t = (((long long)((a - mean) * inv) * (long long)w4.x) >> ts) + b4.x;
            o.x = (float)t * 0.00390625f;
            t = (((long long)((b - mean) * inv) * (long long)w4.y) >> ts) + b4.y;
            o.y = (float)t * 0.00390625f;
            t = (((long long)((c - mean) * inv) * (long long)w4.z) >> ts) + b4.z;
            o.z = (float)t * 0.00390625f;
            t = (((long long)((d - mean) * inv) * (long long)w4.w) >> ts) + b4.w;
            o.w = (float)t * 0.00390625f;
            orow[c4] = o;
        }

        cur ^= 1;
    }
}

extern "C" void kernel_launch(void* const* d_in, const int* in_sizes, int n_in,
                              void* d_out, int out_size) {
    const float* x      = (const float*)d_in[0];
    const float* weight = (const float*)d_in[1];
    const float* bias   = (const float*)d_in[2];
    // d_in[3] (isqrt_lut) intentionally unused: LUT recomputed exactly in-kernel.
    float* out = (float*)d_out;

    const int n_rows = in_sizes[0] / DIM;
    iln_kernel<<<GRID_BLOCKS, NTHREADS>>>(x, weight, bias, out, n_rows);
}